// round 12
// baseline (speedup 1.0000x reference)
#include <cuda_runtime.h>
#include <cuda_bf16.h>
#include <cstdint>

#define B_    16
#define CIN_  512
#define COUT_ 3
#define WDIM_ 512
#define HW_   16384
#define HW4_  4096

#define FC_GAIN_     0.044194173824159216f
#define WEIGHT_GAIN_ 0.044194173824159216f
#define CLAMP_       256.0f

#define CHUNK_   8
#define NCHUNK_  (CIN_ / CHUNK_)
#define NBLOCKS_ (B_ * (HW4_ / 64))   // 1024
#define L2PF_    64                    // channels 16..79 (chunks 2..9) -> L2

// Per-sample modulated 1x1 conv weights: [B][CIN] x float4 (w_o0, w_o1, w_o2, pad)
__device__ float4 g_wmod[B_ * CIN_];
__device__ unsigned g_count = 0;   // styles blocks published
__device__ unsigned g_done  = 0;   // blocks finished (graph-replay reset)

__device__ __forceinline__ void cp_async16(uint32_t smem_addr, const void* gptr) {
    asm volatile("cp.async.cg.shared.global [%0], [%1], 16;"
                 :: "r"(smem_addr), "l"(gptr) : "memory");
}
__device__ __forceinline__ void l2_prefetch(const void* gptr) {
    asm volatile("prefetch.global.L2 [%0];" :: "l"(gptr));
}

// ---------------------------------------------------------------------------
// Fused kernel, grid = 1024 x 64.
//   1) styles operand loads (latency-critical, queue head)
//   2) cp.async chunks 0,1 (16 KB smem prefetch)
//   3) prefetch.global.L2 for chunks 2..9 (64 KB/block, fire-and-forget)
//      -> HBM streams useful data DURING the styles+barrier phase instead
//         of idling (the R6-R11 invariant: DRAM-active was constant, the
//         fusion loss was pure DRAM idle while smem prefetch was capped)
//   4) styles dots + interleaved reductions, publish, spin barrier
//   5) conv main loop (chunks 2..9 cp.async now hit L2)
// 25 KB smem -> 9 blocks/SM, 1332 slots >= 1024: whole grid co-resident.
// ---------------------------------------------------------------------------
__global__ __launch_bounds__(64)
void fused_kernel(const float* __restrict__ x,
                  const float* __restrict__ w,
                  const float* __restrict__ aW,
                  const float* __restrict__ ab,
                  const float* __restrict__ cw,
                  const float* __restrict__ cb,
                  float* __restrict__ out) {
    const int bid = blockIdx.x;
    const int t   = threadIdx.x;
    const int b   = bid >> 6;
    const int p   = (bid & 63) * 64 + t;          // float4 pixel index

    __shared__ float4 swm[CIN_];
    __shared__ float4 stage[2][CHUNK_][64];

    const float4* __restrict__ xb =
        reinterpret_cast<const float4*>(x) + (size_t)b * CIN_ * HW4_ + p;
    const uint32_t stbase = (uint32_t)__cvta_generic_to_shared(&stage[0][0][t]);

    // ---- styles task: c = bid>>1, batches bs..bs+3 per warp ----
    const int c    = bid >> 1;
    const int warp = t >> 5;
    const int lane = t & 31;
    const int bs   = (bid & 1) * 8 + warp * 4;

    const float4* __restrict__ r0 = reinterpret_cast<const float4*>(aW + (size_t)(0 * CIN_ + c) * WDIM_);
    const float4* __restrict__ r1 = reinterpret_cast<const float4*>(aW + (size_t)(1 * CIN_ + c) * WDIM_);
    const float4* __restrict__ r2 = reinterpret_cast<const float4*>(aW + (size_t)(2 * CIN_ + c) * WDIM_);

    // ---- 1) hoisted styles loads (latency-critical) ----
    float4 A0[4], A1[4], A2[4];
    float4 W[4][4];
#pragma unroll
    for (int i = 0; i < 4; i++) {
        const int j = i * 32 + lane;
        A0[i] = r0[j];
        A1[i] = r1[j];
        A2[i] = r2[j];
    }
#pragma unroll
    for (int bb = 0; bb < 4; bb++) {
        const float4* __restrict__ w4 =
            reinterpret_cast<const float4*>(w + (size_t)(bs + bb) * WDIM_);
#pragma unroll
        for (int i = 0; i < 4; i++)
            W[bb][i] = w4[i * 32 + lane];
    }
    const float ab0 = ab[0 * CIN_ + c];
    const float ab1 = ab[1 * CIN_ + c];
    const float ab2 = ab[2 * CIN_ + c];
    const float cw0 = cw[0 * CIN_ + c];
    const float cw1 = cw[1 * CIN_ + c];
    const float cw2 = cw[2 * CIN_ + c];

    // ---- 2) smem prefetch: chunk 0 -> buf0 (G0), chunk 1 -> buf1 (G1) ----
#pragma unroll
    for (int i = 0; i < CHUNK_; i++)
        cp_async16(stbase + i * 1024, xb + (size_t)i * HW4_);
    asm volatile("cp.async.commit_group;" ::: "memory");
#pragma unroll
    for (int i = 0; i < CHUNK_; i++)
        cp_async16(stbase + (CHUNK_ * 1024) + i * 1024,
                   xb + (size_t)(CHUNK_ + i) * HW4_);
    asm volatile("cp.async.commit_group;" ::: "memory");

    // ---- 3) L2 prefetch: chunks 2..9 (keeps HBM busy through styles) ----
#pragma unroll
    for (int i = 0; i < L2PF_; i++)
        l2_prefetch(xb + (size_t)(2 * CHUNK_ + i) * HW4_);

    // ---- 4) styles dots + interleaved reductions ----
    {
        float s[4][3];
#pragma unroll
        for (int bb = 0; bb < 4; bb++)
            s[bb][0] = s[bb][1] = s[bb][2] = 0.f;

#pragma unroll
        for (int bb = 0; bb < 4; bb++)
#pragma unroll
            for (int i = 0; i < 4; i++) {
                float4 wv = W[bb][i];
                s[bb][0] += wv.x * A0[i].x + wv.y * A0[i].y + wv.z * A0[i].z + wv.w * A0[i].w;
                s[bb][1] += wv.x * A1[i].x + wv.y * A1[i].y + wv.z * A1[i].z + wv.w * A1[i].w;
                s[bb][2] += wv.x * A2[i].x + wv.y * A2[i].y + wv.z * A2[i].z + wv.w * A2[i].w;
            }

#pragma unroll
        for (int off = 16; off > 0; off >>= 1)
#pragma unroll
            for (int bb = 0; bb < 4; bb++) {
                s[bb][0] += __shfl_xor_sync(0xFFFFFFFF, s[bb][0], off);
                s[bb][1] += __shfl_xor_sync(0xFFFFFFFF, s[bb][1], off);
                s[bb][2] += __shfl_xor_sync(0xFFFFFFFF, s[bb][2], off);
            }

        if (lane == 0) {
#pragma unroll
            for (int bb = 0; bb < 4; bb++) {
                float m1 = s[bb][0] * FC_GAIN_ + ab0;
                float m2 = s[bb][1] * FC_GAIN_ + ab1;
                float m3 = s[bb][2] * FC_GAIN_ + ab2;
                float st = (m1 * m2 + m3) * WEIGHT_GAIN_;
                g_wmod[(bs + bb) * CIN_ + c] =
                    make_float4(cw0 * st, cw1 * st, cw2 * st, 0.f);
            }
        }
        __syncthreads();
        if (t == 0) {
            __threadfence();
            atomicAdd(&g_count, 1u);
        }
    }

    // ---- barrier: wait for all 1024 publications, then load swm ----
    if (t == 0) {
        unsigned v;
        do {
            asm volatile("ld.acquire.gpu.global.u32 %0, [%1];"
                         : "=r"(v) : "l"(&g_count) : "memory");
        } while (v < NBLOCKS_);
    }
    __syncthreads();

    {
        const float4* gw = g_wmod + b * CIN_;
#pragma unroll
        for (int i = 0; i < CIN_ / 64; i++)
            swm[i * 64 + t] = gw[i * 64 + t];
    }
    __syncthreads();

    // ---- 5) conv main loop: chunk k in buf[k&1]; refill with k+2 after
    //         consuming k. wait_group 1 => chunk k ready.
    float4 a0 = make_float4(0.f, 0.f, 0.f, 0.f);
    float4 a1 = a0;
    float4 a2 = a0;

    for (int k = 0; k < NCHUNK_; k++) {
        const int cur = k & 1;
        if (k + 1 < NCHUNK_) {
            asm volatile("cp.async.wait_group 1;" ::: "memory");
        } else {
            asm volatile("cp.async.wait_group 0;" ::: "memory");
        }

#pragma unroll
        for (int i = 0; i < CHUNK_; i++) {
            float4 xv = stage[cur][i][t];
            float4 wm = swm[k * CHUNK_ + i];
            a0.x = fmaf(xv.x, wm.x, a0.x);
            a0.y = fmaf(xv.y, wm.x, a0.y);
            a0.z = fmaf(xv.z, wm.x, a0.z);
            a0.w = fmaf(xv.w, wm.x, a0.w);
            a1.x = fmaf(xv.x, wm.y, a1.x);
            a1.y = fmaf(xv.y, wm.y, a1.y);
            a1.z = fmaf(xv.z, wm.y, a1.z);
            a1.w = fmaf(xv.w, wm.y, a1.w);
            a2.x = fmaf(xv.x, wm.z, a2.x);
            a2.y = fmaf(xv.y, wm.z, a2.y);
            a2.z = fmaf(xv.z, wm.z, a2.z);
            a2.w = fmaf(xv.w, wm.z, a2.w);
        }

        if (k + 2 < NCHUNK_) {
            const int c2 = (k + 2) * CHUNK_;
            const uint32_t sb = stbase + cur * (CHUNK_ * 1024);
#pragma unroll
            for (int i = 0; i < CHUNK_; i++)
                cp_async16(sb + i * 1024, xb + (size_t)(c2 + i) * HW4_);
            asm volatile("cp.async.commit_group;" ::: "memory");
        }
    }

    const float b0 = cb[0], b1 = cb[1], b2 = cb[2];

    a0.x = fminf(fmaxf(a0.x + b0, -CLAMP_), CLAMP_);
    a0.y = fminf(fmaxf(a0.y + b0, -CLAMP_), CLAMP_);
    a0.z = fminf(fmaxf(a0.z + b0, -CLAMP_), CLAMP_);
    a0.w = fminf(fmaxf(a0.w + b0, -CLAMP_), CLAMP_);

    a1.x = fminf(fmaxf(a1.x + b1, -CLAMP_), CLAMP_);
    a1.y = fminf(fmaxf(a1.y + b1, -CLAMP_), CLAMP_);
    a1.z = fminf(fmaxf(a1.z + b1, -CLAMP_), CLAMP_);
    a1.w = fminf(fmaxf(a1.w + b1, -CLAMP_), CLAMP_);

    a2.x = fminf(fmaxf(a2.x + b2, -CLAMP_), CLAMP_);
    a2.y = fminf(fmaxf(a2.y + b2, -CLAMP_), CLAMP_);
    a2.z = fminf(fmaxf(a2.z + b2, -CLAMP_), CLAMP_);
    a2.w = fminf(fmaxf(a2.w + b2, -CLAMP_), CLAMP_);

    float4* __restrict__ o =
        reinterpret_cast<float4*>(out) + (size_t)b * COUT_ * HW4_ + p;
    o[0 * HW4_] = a0;
    o[1 * HW4_] = a1;
    o[2 * HW4_] = a2;

    // ---- reset flags for next graph replay (last block out) ----
    __syncthreads();
    if (t == 0) {
        __threadfence();
        unsigned d = atomicAdd(&g_done, 1u);
        if (d == NBLOCKS_ - 1) {
            g_count = 0;
            g_done  = 0;
            __threadfence();
        }
    }
}

// ---------------------------------------------------------------------------
// inputs (metadata order): x, w, affine_W, affine_b, conv_w, conv_b
// ---------------------------------------------------------------------------
extern "C" void kernel_launch(void* const* d_in, const int* in_sizes, int n_in,
                              void* d_out, int out_size) {
    const float* x  = (const float*)d_in[0];
    const float* w  = (const float*)d_in[1];
    const float* aW = (const float*)d_in[2];
    const float* ab = (const float*)d_in[3];
    const float* cw = (const float*)d_in[4];
    const float* cb = (const float*)d_in[5];
    float* out = (float*)d_out;

    fused_kernel<<<NBLOCKS_, 64>>>(x, w, aW, ab, cw, cb, out);
}

// round 13
// speedup vs baseline: 1.0210x; 1.0210x over previous
#include <cuda_runtime.h>
#include <cuda_bf16.h>
#include <cstdint>

#define B_    16
#define CIN_  512
#define COUT_ 3
#define WDIM_ 512
#define HW_   16384
#define HW4_  4096

#define FC_GAIN_     0.044194173824159216f
#define WEIGHT_GAIN_ 0.044194173824159216f
#define CLAMP_       256.0f

#define CHUNK_   8
#define NCHUNK_  (CIN_ / CHUNK_)
#define NBLOCKS_ (B_ * (HW4_ / 64))   // 1024

// Per-sample modulated 1x1 conv weights: [B][CIN] x float4 (w_o0, w_o1, w_o2, pad)
__device__ float4 g_wmod[B_ * CIN_];
__device__ unsigned g_count = 0;   // styles blocks published
__device__ unsigned g_done  = 0;   // blocks finished (graph-replay reset)

__device__ __forceinline__ void cp_async16(uint32_t smem_addr, const void* gptr) {
    asm volatile("cp.async.cg.shared.global [%0], [%1], 16;"
                 :: "r"(smem_addr), "l"(gptr) : "memory");
}

// ---------------------------------------------------------------------------
// Fused kernel, grid = 1024 x 64. Phase order is the entire point:
//   1) styles operand loads  -- NOTHING else in the LSU queue, arrive fast
//   2) styles dots + interleaved reductions + publish  (~1 us)
//   3) THEN cp.async chunks 0,1  (pipeline fill = DRAM-useful work that a
//      standalone conv kernel also pays)
//   4) global spin barrier, swm load, conv main loop
// R6-R12 showed DRAM-active is invariant (~68.5us); the fused losses were
// styles loads drowning behind ~100 KB/SM of cp.async from co-resident
// blocks. Issuing ZERO cp.async before styles completes removes that.
// 25 KB smem -> 9 blocks/SM, 1332 slots >= 1024: whole grid co-resident.
// ---------------------------------------------------------------------------
__global__ __launch_bounds__(64)
void fused_kernel(const float* __restrict__ x,
                  const float* __restrict__ w,
                  const float* __restrict__ aW,
                  const float* __restrict__ ab,
                  const float* __restrict__ cw,
                  const float* __restrict__ cb,
                  float* __restrict__ out) {
    const int bid = blockIdx.x;
    const int t   = threadIdx.x;
    const int b   = bid >> 6;
    const int p   = (bid & 63) * 64 + t;          // float4 pixel index

    __shared__ float4 swm[CIN_];
    __shared__ float4 stage[2][CHUNK_][64];

    const float4* __restrict__ xb =
        reinterpret_cast<const float4*>(x) + (size_t)b * CIN_ * HW4_ + p;
    const uint32_t stbase = (uint32_t)__cvta_generic_to_shared(&stage[0][0][t]);

    // ---- styles task: c = bid>>1, batches bs..bs+3 per warp ----
    const int c    = bid >> 1;
    const int warp = t >> 5;
    const int lane = t & 31;
    const int bs   = (bid & 1) * 8 + warp * 4;

    const float4* __restrict__ r0 = reinterpret_cast<const float4*>(aW + (size_t)(0 * CIN_ + c) * WDIM_);
    const float4* __restrict__ r1 = reinterpret_cast<const float4*>(aW + (size_t)(1 * CIN_ + c) * WDIM_);
    const float4* __restrict__ r2 = reinterpret_cast<const float4*>(aW + (size_t)(2 * CIN_ + c) * WDIM_);

    // ---- 1) styles loads with an empty memory queue ----
    float4 A0[4], A1[4], A2[4];
    float4 W[4][4];
#pragma unroll
    for (int i = 0; i < 4; i++) {
        const int j = i * 32 + lane;
        A0[i] = r0[j];
        A1[i] = r1[j];
        A2[i] = r2[j];
    }
#pragma unroll
    for (int bb = 0; bb < 4; bb++) {
        const float4* __restrict__ w4 =
            reinterpret_cast<const float4*>(w + (size_t)(bs + bb) * WDIM_);
#pragma unroll
        for (int i = 0; i < 4; i++)
            W[bb][i] = w4[i * 32 + lane];
    }
    const float ab0 = ab[0 * CIN_ + c];
    const float ab1 = ab[1 * CIN_ + c];
    const float ab2 = ab[2 * CIN_ + c];
    const float cw0 = cw[0 * CIN_ + c];
    const float cw1 = cw[1 * CIN_ + c];
    const float cw2 = cw[2 * CIN_ + c];

    // ---- 2) styles dots + interleaved reductions + publish ----
    {
        float s[4][3];
#pragma unroll
        for (int bb = 0; bb < 4; bb++)
            s[bb][0] = s[bb][1] = s[bb][2] = 0.f;

#pragma unroll
        for (int bb = 0; bb < 4; bb++)
#pragma unroll
            for (int i = 0; i < 4; i++) {
                float4 wv = W[bb][i];
                s[bb][0] += wv.x * A0[i].x + wv.y * A0[i].y + wv.z * A0[i].z + wv.w * A0[i].w;
                s[bb][1] += wv.x * A1[i].x + wv.y * A1[i].y + wv.z * A1[i].z + wv.w * A1[i].w;
                s[bb][2] += wv.x * A2[i].x + wv.y * A2[i].y + wv.z * A2[i].z + wv.w * A2[i].w;
            }

#pragma unroll
        for (int off = 16; off > 0; off >>= 1)
#pragma unroll
            for (int bb = 0; bb < 4; bb++) {
                s[bb][0] += __shfl_xor_sync(0xFFFFFFFF, s[bb][0], off);
                s[bb][1] += __shfl_xor_sync(0xFFFFFFFF, s[bb][1], off);
                s[bb][2] += __shfl_xor_sync(0xFFFFFFFF, s[bb][2], off);
            }

        if (lane == 0) {
#pragma unroll
            for (int bb = 0; bb < 4; bb++) {
                float m1 = s[bb][0] * FC_GAIN_ + ab0;
                float m2 = s[bb][1] * FC_GAIN_ + ab1;
                float m3 = s[bb][2] * FC_GAIN_ + ab2;
                float st = (m1 * m2 + m3) * WEIGHT_GAIN_;
                g_wmod[(bs + bb) * CIN_ + c] =
                    make_float4(cw0 * st, cw1 * st, cw2 * st, 0.f);
            }
        }
        __syncthreads();
        if (t == 0) {
            __threadfence();
            atomicAdd(&g_count, 1u);
        }
    }

    // ---- 3) NOW start the conv prefetch: chunks 0,1 -> buffers 0,1 ----
#pragma unroll
    for (int i = 0; i < CHUNK_; i++)
        cp_async16(stbase + i * 1024, xb + (size_t)i * HW4_);
    asm volatile("cp.async.commit_group;" ::: "memory");
#pragma unroll
    for (int i = 0; i < CHUNK_; i++)
        cp_async16(stbase + (CHUNK_ * 1024) + i * 1024,
                   xb + (size_t)(CHUNK_ + i) * HW4_);
    asm volatile("cp.async.commit_group;" ::: "memory");

    // ---- 4) barrier: wait for all 1024 publications, then load swm ----
    if (t == 0) {
        unsigned v;
        do {
            asm volatile("ld.acquire.gpu.global.u32 %0, [%1];"
                         : "=r"(v) : "l"(&g_count) : "memory");
        } while (v < NBLOCKS_);
    }
    __syncthreads();

    {
        const float4* gw = g_wmod + b * CIN_;
#pragma unroll
        for (int i = 0; i < CIN_ / 64; i++)
            swm[i * 64 + t] = gw[i * 64 + t];
    }
    __syncthreads();

    // ---- conv main loop: chunk k in buf[k&1]; refill with k+2 after
    //      consuming k. wait_group 1 => chunk k ready.
    float4 a0 = make_float4(0.f, 0.f, 0.f, 0.f);
    float4 a1 = a0;
    float4 a2 = a0;

    for (int k = 0; k < NCHUNK_; k++) {
        const int cur = k & 1;
        if (k + 1 < NCHUNK_) {
            asm volatile("cp.async.wait_group 1;" ::: "memory");
        } else {
            asm volatile("cp.async.wait_group 0;" ::: "memory");
        }

#pragma unroll
        for (int i = 0; i < CHUNK_; i++) {
            float4 xv = stage[cur][i][t];
            float4 wm = swm[k * CHUNK_ + i];
            a0.x = fmaf(xv.x, wm.x, a0.x);
            a0.y = fmaf(xv.y, wm.x, a0.y);
            a0.z = fmaf(xv.z, wm.x, a0.z);
            a0.w = fmaf(xv.w, wm.x, a0.w);
            a1.x = fmaf(xv.x, wm.y, a1.x);
            a1.y = fmaf(xv.y, wm.y, a1.y);
            a1.z = fmaf(xv.z, wm.y, a1.z);
            a1.w = fmaf(xv.w, wm.y, a1.w);
            a2.x = fmaf(xv.x, wm.z, a2.x);
            a2.y = fmaf(xv.y, wm.z, a2.y);
            a2.z = fmaf(xv.z, wm.z, a2.z);
            a2.w = fmaf(xv.w, wm.z, a2.w);
        }

        if (k + 2 < NCHUNK_) {
            const int c2 = (k + 2) * CHUNK_;
            const uint32_t sb = stbase + cur * (CHUNK_ * 1024);
#pragma unroll
            for (int i = 0; i < CHUNK_; i++)
                cp_async16(sb + i * 1024, xb + (size_t)(c2 + i) * HW4_);
            asm volatile("cp.async.commit_group;" ::: "memory");
        }
    }

    const float b0 = cb[0], b1 = cb[1], b2 = cb[2];

    a0.x = fminf(fmaxf(a0.x + b0, -CLAMP_), CLAMP_);
    a0.y = fminf(fmaxf(a0.y + b0, -CLAMP_), CLAMP_);
    a0.z = fminf(fmaxf(a0.z + b0, -CLAMP_), CLAMP_);
    a0.w = fminf(fmaxf(a0.w + b0, -CLAMP_), CLAMP_);

    a1.x = fminf(fmaxf(a1.x + b1, -CLAMP_), CLAMP_);
    a1.y = fminf(fmaxf(a1.y + b1, -CLAMP_), CLAMP_);
    a1.z = fminf(fmaxf(a1.z + b1, -CLAMP_), CLAMP_);
    a1.w = fminf(fmaxf(a1.w + b1, -CLAMP_), CLAMP_);

    a2.x = fminf(fmaxf(a2.x + b2, -CLAMP_), CLAMP_);
    a2.y = fminf(fmaxf(a2.y + b2, -CLAMP_), CLAMP_);
    a2.z = fminf(fmaxf(a2.z + b2, -CLAMP_), CLAMP_);
    a2.w = fminf(fmaxf(a2.w + b2, -CLAMP_), CLAMP_);

    float4* __restrict__ o =
        reinterpret_cast<float4*>(out) + (size_t)b * COUT_ * HW4_ + p;
    o[0 * HW4_] = a0;
    o[1 * HW4_] = a1;
    o[2 * HW4_] = a2;

    // ---- reset flags for next graph replay (last block out) ----
    __syncthreads();
    if (t == 0) {
        __threadfence();
        unsigned d = atomicAdd(&g_done, 1u);
        if (d == NBLOCKS_ - 1) {
            g_count = 0;
            g_done  = 0;
            __threadfence();
        }
    }
}

// ---------------------------------------------------------------------------
// inputs (metadata order): x, w, affine_W, affine_b, conv_w, conv_b
// ---------------------------------------------------------------------------
extern "C" void kernel_launch(void* const* d_in, const int* in_sizes, int n_in,
                              void* d_out, int out_size) {
    const float* x  = (const float*)d_in[0];
    const float* w  = (const float*)d_in[1];
    const float* aW = (const float*)d_in[2];
    const float* ab = (const float*)d_in[3];
    const float* cw = (const float*)d_in[4];
    const float* cb = (const float*)d_in[5];
    float* out = (float*)d_out;

    fused_kernel<<<NBLOCKS_, 64>>>(x, w, aW, ab, cw, cb, out);
}

// round 14
// speedup vs baseline: 1.0457x; 1.0242x over previous
#include <cuda_runtime.h>
#include <cuda_bf16.h>
#include <cstdint>

#define B_    16
#define CIN_  512
#define COUT_ 3
#define WDIM_ 512
#define HW_   16384
#define HW4_  4096

#define FC_GAIN_     0.044194173824159216f
#define WEIGHT_GAIN_ 0.044194173824159216f
#define CLAMP_       256.0f

#define CHUNK_  8
#define NCHUNK_ (CIN_ / CHUNK_)

// Per-sample modulated 1x1 conv weights: [B][CIN] x float4 (w_o0, w_o1, w_o2, pad)
__device__ float4 g_wmod[B_ * CIN_];

__device__ __forceinline__ void cp_async16(uint32_t smem_addr, const void* gptr) {
    asm volatile("cp.async.cg.shared.global [%0], [%1], 16;"
                 :: "r"(smem_addr), "l"(gptr) : "memory");
}

// ---------------------------------------------------------------------------
// Kernel 1: styles + weight modulation. Block per channel c: the 3 affine_W
// rows are loaded to smem ONCE and reused for all 16 batches (w vectors are
// L2-resident). DRAM traffic ~3 MB. (R5-proven configuration.)
// grid = CIN_, block = 128 (4 warps x 4 batches each).
// ---------------------------------------------------------------------------
__global__ __launch_bounds__(128)
void styles_kernel(const float* __restrict__ w,
                   const float* __restrict__ aW,
                   const float* __restrict__ ab,
                   const float* __restrict__ cw) {
    const int c    = blockIdx.x;
    const int t    = threadIdx.x;
    const int warp = t >> 5;
    const int lane = t & 31;

    __shared__ float4 r0s[WDIM_ / 4];
    __shared__ float4 r1s[WDIM_ / 4];
    __shared__ float4 r2s[WDIM_ / 4];

    {
        const float4* __restrict__ r0 = reinterpret_cast<const float4*>(aW + (size_t)(0 * CIN_ + c) * WDIM_);
        const float4* __restrict__ r1 = reinterpret_cast<const float4*>(aW + (size_t)(1 * CIN_ + c) * WDIM_);
        const float4* __restrict__ r2 = reinterpret_cast<const float4*>(aW + (size_t)(2 * CIN_ + c) * WDIM_);
        r0s[t] = r0[t];
        r1s[t] = r1[t];
        r2s[t] = r2[t];
    }
    __syncthreads();

    const float ab0 = ab[0 * CIN_ + c];
    const float ab1 = ab[1 * CIN_ + c];
    const float ab2 = ab[2 * CIN_ + c];
    const float cw0 = cw[0 * CIN_ + c];
    const float cw1 = cw[1 * CIN_ + c];
    const float cw2 = cw[2 * CIN_ + c];

#pragma unroll
    for (int bb = 0; bb < B_ / 4; bb++) {
        const int b = warp * 4 + bb;
        const float4* __restrict__ w4 = reinterpret_cast<const float4*>(w + (size_t)b * WDIM_);

        float s0 = 0.f, s1 = 0.f, s2 = 0.f;
#pragma unroll
        for (int jj = 0; jj < WDIM_ / 4 / 32; jj++) {     // 4 iterations
            const int j = jj * 32 + lane;
            float4 wv = w4[j];
            float4 a0 = r0s[j];
            float4 a1 = r1s[j];
            float4 a2 = r2s[j];
            s0 += wv.x * a0.x + wv.y * a0.y + wv.z * a0.z + wv.w * a0.w;
            s1 += wv.x * a1.x + wv.y * a1.y + wv.z * a1.z + wv.w * a1.w;
            s2 += wv.x * a2.x + wv.y * a2.y + wv.z * a2.z + wv.w * a2.w;
        }

#pragma unroll
        for (int off = 16; off > 0; off >>= 1) {
            s0 += __shfl_xor_sync(0xFFFFFFFF, s0, off);
            s1 += __shfl_xor_sync(0xFFFFFFFF, s1, off);
            s2 += __shfl_xor_sync(0xFFFFFFFF, s2, off);
        }

        if (lane == 0) {
            float m1 = s0 * FC_GAIN_ + ab0;
            float m2 = s1 * FC_GAIN_ + ab1;
            float m3 = s2 * FC_GAIN_ + ab2;
            float st = (m1 * m2 + m3) * WEIGHT_GAIN_;
            g_wmod[b * CIN_ + c] = make_float4(cw0 * st, cw1 * st, cw2 * st, 0.f);
        }
    }
}

// ---------------------------------------------------------------------------
// Kernel 2: streaming modulated 1x1 conv, cp.async double-buffered
// (R5-proven: 25 KB smem -> 9 resident blocks/SM, single fluid wave,
// ~85% of HBM spec). Sole refinement vs R5: the chunk-0 prefetch group is
// issued BEFORE staging swm, so the DRAM pipeline fill starts immediately
// and the g_wmod L2-hit latency overlaps it (R7's conv body, 79.84us).
// grid = (64, B), block = 64.
// ---------------------------------------------------------------------------
__global__ __launch_bounds__(64)
void conv_kernel(const float* __restrict__ x,
                 const float* __restrict__ cb,
                 float* __restrict__ out) {
    const int b = blockIdx.y;
    const int t = threadIdx.x;
    const int p = blockIdx.x * 64 + t;            // float4 pixel index

    __shared__ float4 swm[CIN_];
    __shared__ float4 stage[2][CHUNK_][64];

    const float4* __restrict__ xb =
        reinterpret_cast<const float4*>(x) + (size_t)b * CIN_ * HW4_ + p;

    const uint32_t stbase = (uint32_t)__cvta_generic_to_shared(&stage[0][0][t]);

    // Prologue: prefetch chunk 0 into buffer 0 (before swm staging)
#pragma unroll
    for (int i = 0; i < CHUNK_; i++)
        cp_async16(stbase + i * 1024, xb + (size_t)i * HW4_);
    asm volatile("cp.async.commit_group;" ::: "memory");

    {
        const float4* gw = g_wmod + b * CIN_;
#pragma unroll
        for (int i = 0; i < CIN_ / 64; i++)
            swm[i * 64 + t] = gw[i * 64 + t];
    }
    __syncthreads();

    float4 a0 = make_float4(0.f, 0.f, 0.f, 0.f);
    float4 a1 = a0;
    float4 a2 = a0;

    for (int k = 0; k < NCHUNK_; k++) {
        const int cur = k & 1;
        if (k + 1 < NCHUNK_) {
            const int c1 = (k + 1) * CHUNK_;
            const uint32_t sb = stbase + (cur ^ 1) * (CHUNK_ * 1024);
#pragma unroll
            for (int i = 0; i < CHUNK_; i++)
                cp_async16(sb + i * 1024, xb + (size_t)(c1 + i) * HW4_);
            asm volatile("cp.async.commit_group;" ::: "memory");
            asm volatile("cp.async.wait_group 1;" ::: "memory");
        } else {
            asm volatile("cp.async.wait_group 0;" ::: "memory");
        }

#pragma unroll
        for (int i = 0; i < CHUNK_; i++) {
            float4 xv = stage[cur][i][t];
            float4 wm = swm[k * CHUNK_ + i];
            a0.x = fmaf(xv.x, wm.x, a0.x);
            a0.y = fmaf(xv.y, wm.x, a0.y);
            a0.z = fmaf(xv.z, wm.x, a0.z);
            a0.w = fmaf(xv.w, wm.x, a0.w);
            a1.x = fmaf(xv.x, wm.y, a1.x);
            a1.y = fmaf(xv.y, wm.y, a1.y);
            a1.z = fmaf(xv.z, wm.y, a1.z);
            a1.w = fmaf(xv.w, wm.y, a1.w);
            a2.x = fmaf(xv.x, wm.z, a2.x);
            a2.y = fmaf(xv.y, wm.z, a2.y);
            a2.z = fmaf(xv.z, wm.z, a2.z);
            a2.w = fmaf(xv.w, wm.z, a2.w);
        }
    }

    const float b0 = cb[0], b1 = cb[1], b2 = cb[2];

    a0.x = fminf(fmaxf(a0.x + b0, -CLAMP_), CLAMP_);
    a0.y = fminf(fmaxf(a0.y + b0, -CLAMP_), CLAMP_);
    a0.z = fminf(fmaxf(a0.z + b0, -CLAMP_), CLAMP_);
    a0.w = fminf(fmaxf(a0.w + b0, -CLAMP_), CLAMP_);

    a1.x = fminf(fmaxf(a1.x + b1, -CLAMP_), CLAMP_);
    a1.y = fminf(fmaxf(a1.y + b1, -CLAMP_), CLAMP_);
    a1.z = fminf(fmaxf(a1.z + b1, -CLAMP_), CLAMP_);
    a1.w = fminf(fmaxf(a1.w + b1, -CLAMP_), CLAMP_);

    a2.x = fminf(fmaxf(a2.x + b2, -CLAMP_), CLAMP_);
    a2.y = fminf(fmaxf(a2.y + b2, -CLAMP_), CLAMP_);
    a2.z = fminf(fmaxf(a2.z + b2, -CLAMP_), CLAMP_);
    a2.w = fminf(fmaxf(a2.w + b2, -CLAMP_), CLAMP_);

    float4* __restrict__ o =
        reinterpret_cast<float4*>(out) + (size_t)b * COUT_ * HW4_ + p;
    o[0 * HW4_] = a0;
    o[1 * HW4_] = a1;
    o[2 * HW4_] = a2;
}

// ---------------------------------------------------------------------------
// inputs (metadata order): x, w, affine_W, affine_b, conv_w, conv_b
// ---------------------------------------------------------------------------
extern "C" void kernel_launch(void* const* d_in, const int* in_sizes, int n_in,
                              void* d_out, int out_size) {
    const float* x  = (const float*)d_in[0];
    const float* w  = (const float*)d_in[1];
    const float* aW = (const float*)d_in[2];
    const float* ab = (const float*)d_in[3];
    const float* cw = (const float*)d_in[4];
    const float* cb = (const float*)d_in[5];
    float* out = (float*)d_out;

    styles_kernel<<<CIN_, 128>>>(w, aW, ab, cw);
    {
        dim3 grid(HW4_ / 64, B_);
        conv_kernel<<<grid, 64>>>(x, cb, out);
    }
}